// round 1
// baseline (speedup 1.0000x reference)
#include <cuda_runtime.h>
#include <cstdint>

// ============================================================================
// AdditiveAttention: out = softmax_mask( sum_h tanh(Q@Wq + K@Wk) * wv ) @ V
// B=16, Q=128, K=128, D=512, H=512
// Plan:
//   kernel 1 (sgemm_proj): Qp = queries@Wq, Kp = keys@Wk  (one launch, z=0/1)
//   kernel 2 (attn_kernel): per (b, 16-row q-tile): scores (tanh-reduce over h),
//                           masked softmax over all 128 k, then attn @ values.
// ============================================================================

#define BDIM 16
#define QDIM 128
#define KDIM 128
#define DDIM 512
#define HDIM 512

// scratch for projected Q and K (allocation-free rule: __device__ globals)
__device__ float g_Qp[BDIM * QDIM * HDIM];   // [b*128+q][h], 4 MB
__device__ float g_Kp[BDIM * KDIM * HDIM];   // [b*128+k][h], 4 MB

__device__ __forceinline__ float tanh_fast(float x) {
    float y;
    asm("tanh.approx.f32 %0, %1;" : "=f"(y) : "f"(x));
    return y;
}

// ----------------------------------------------------------------------------
// Kernel 1: C[M,N] = A[M,K] * W[K,N]   with M=2048, K=512, N=512
// 128x128 tile, BK=16, 256 threads, 8x8 micro-tile, register prefetch.
// blockIdx.z = 0 -> queries@Wq -> g_Qp ; 1 -> keys@Wk -> g_Kp
// ----------------------------------------------------------------------------
__global__ __launch_bounds__(256, 1) void sgemm_proj(
    const float* __restrict__ Aq, const float* __restrict__ Ak,
    const float* __restrict__ Wq, const float* __restrict__ Wk)
{
    const int M = BDIM * QDIM;   // 2048
    const int K = DDIM;          // 512
    const int N = HDIM;          // 512

    const float* A = blockIdx.z ? Ak : Aq;
    const float* W = blockIdx.z ? Wk : Wq;
    float* C = blockIdx.z ? g_Kp : g_Qp;

    __shared__ __align__(16) float As[16][132];   // transposed: As[k][m]
    __shared__ __align__(16) float Ws[16][128];   // Ws[k][n]

    const int tid = threadIdx.x;
    const int tx = tid & 15;        // 0..15  (col block)
    const int ty = tid >> 4;        // 0..15  (row block)
    const int m0 = blockIdx.y * 128;
    const int n0 = blockIdx.x * 128;

    // global load coords
    const int arow = tid >> 2;            // 0..63 (and +64)
    const int ac   = (tid & 3) << 2;      // 0,4,8,12
    const int wk   = tid >> 5;            // 0..7 (and +8)
    const int wn   = (tid & 31) << 2;     // 0..124

    float acc[8][8];
#pragma unroll
    for (int i = 0; i < 8; i++)
#pragma unroll
        for (int j = 0; j < 8; j++) acc[i][j] = 0.0f;

    float4 pa0, pa1, pw0, pw1;

    // prefetch tile 0
    pa0 = *(const float4*)&A[(m0 + arow) * K + 0 + ac];
    pa1 = *(const float4*)&A[(m0 + arow + 64) * K + 0 + ac];
    pw0 = *(const float4*)&W[(0 + wk) * N + n0 + wn];
    pw1 = *(const float4*)&W[(0 + wk + 8) * N + n0 + wn];

    // store tile 0
    As[ac + 0][arow] = pa0.x; As[ac + 1][arow] = pa0.y;
    As[ac + 2][arow] = pa0.z; As[ac + 3][arow] = pa0.w;
    As[ac + 0][arow + 64] = pa1.x; As[ac + 1][arow + 64] = pa1.y;
    As[ac + 2][arow + 64] = pa1.z; As[ac + 3][arow + 64] = pa1.w;
    *(float4*)&Ws[wk][wn] = pw0;
    *(float4*)&Ws[wk + 8][wn] = pw1;
    __syncthreads();

    const int NIT = K / 16;   // 32
    for (int it = 0; it < NIT; ++it) {
        if (it + 1 < NIT) {
            const int kt = (it + 1) * 16;
            pa0 = *(const float4*)&A[(m0 + arow) * K + kt + ac];
            pa1 = *(const float4*)&A[(m0 + arow + 64) * K + kt + ac];
            pw0 = *(const float4*)&W[(kt + wk) * N + n0 + wn];
            pw1 = *(const float4*)&W[(kt + wk + 8) * N + n0 + wn];
        }
#pragma unroll
        for (int kk = 0; kk < 16; ++kk) {
            float a[8], b[8];
            *(float4*)&a[0] = *(const float4*)&As[kk][ty * 8];
            *(float4*)&a[4] = *(const float4*)&As[kk][ty * 8 + 4];
            *(float4*)&b[0] = *(const float4*)&Ws[kk][tx * 8];
            *(float4*)&b[4] = *(const float4*)&Ws[kk][tx * 8 + 4];
#pragma unroll
            for (int i = 0; i < 8; i++)
#pragma unroll
                for (int j = 0; j < 8; j++)
                    acc[i][j] = fmaf(a[i], b[j], acc[i][j]);
        }
        __syncthreads();
        if (it + 1 < NIT) {
            As[ac + 0][arow] = pa0.x; As[ac + 1][arow] = pa0.y;
            As[ac + 2][arow] = pa0.z; As[ac + 3][arow] = pa0.w;
            As[ac + 0][arow + 64] = pa1.x; As[ac + 1][arow + 64] = pa1.y;
            As[ac + 2][arow + 64] = pa1.z; As[ac + 3][arow + 64] = pa1.w;
            *(float4*)&Ws[wk][wn] = pw0;
            *(float4*)&Ws[wk + 8][wn] = pw1;
            __syncthreads();
        }
    }

    // write out
#pragma unroll
    for (int i = 0; i < 8; i++) {
        float* crow = &C[(m0 + ty * 8 + i) * N + n0 + tx * 8];
        *(float4*)&crow[0] = *(float4*)&acc[i][0];
        *(float4*)&crow[4] = *(float4*)&acc[i][4];
    }
}

// ----------------------------------------------------------------------------
// Kernel 2: fused scores + masked softmax + attn@V
// grid = (8 q-tiles, 16 batches), 256 threads (8 warps).
// Each warp owns 2 q-rows; lane tk owns k in {tk, tk+32, tk+64, tk+96}.
// Scores accumulate over h in chunks of HC=32 (smem-staged Qp/Kp tiles).
// ----------------------------------------------------------------------------
#define HC 32
#define KS_STRIDE 36   // 36 % 32 == 4 -> conflict-free LDS.128 pattern

__global__ __launch_bounds__(256, 1) void attn_kernel(
    const float* __restrict__ values,
    const int* __restrict__ valid_lens,
    const float* __restrict__ wv,
    float* __restrict__ out)
{
    const int b  = blockIdx.y;
    const int qt = blockIdx.x;        // 0..7, 16 q-rows each
    const int tid = threadIdx.x;
    const int tk = tid & 31;          // lane
    const int tq = tid >> 5;          // warp id 0..7 -> q rows 2*tq, 2*tq+1

    __shared__ __align__(16) float Ks[128][KS_STRIDE];
    __shared__ __align__(16) float Qs[16][KS_STRIDE];
    __shared__ __align__(16) float wvs[HDIM];
    __shared__ __align__(16) float attnT[128][20];   // [k][q], padded

    // load wv once (512 floats = 128 float4)
    if (tid < 128)
        *(float4*)&wvs[tid * 4] = *(const float4*)&wv[tid * 4];

    const float* Qp = g_Qp + (b * QDIM + qt * 16) * HDIM;
    const float* Kp = g_Kp + b * KDIM * HDIM;

    float s[2][4];
#pragma unroll
    for (int r = 0; r < 2; r++)
#pragma unroll
        for (int j = 0; j < 4; j++) s[r][j] = 0.0f;

    // ---------------- Phase A: scores over h chunks ----------------
    for (int hc = 0; hc < HDIM / HC; ++hc) {
        const int h0 = hc * HC;
        // Qs: 16 rows x 32 = 128 float4 (threads 0..127)
        if (tid < 128) {
            const int q = tid >> 3, h4 = tid & 7;
            *(float4*)&Qs[q][h4 * 4] = *(const float4*)&Qp[q * HDIM + h0 + h4 * 4];
        }
        // Ks: 128 rows x 32 = 1024 float4, 4 per thread
#pragma unroll
        for (int i = 0; i < 4; i++) {
            const int idx = tid + i * 256;
            const int k = idx >> 3, h4 = idx & 7;
            *(float4*)&Ks[k][h4 * 4] = *(const float4*)&Kp[k * HDIM + h0 + h4 * 4];
        }
        __syncthreads();

#pragma unroll
        for (int h4 = 0; h4 < HC / 4; ++h4) {
            const float4 w4 = *(const float4*)&wvs[h0 + h4 * 4];
            const float4 qa = *(const float4*)&Qs[tq * 2][h4 * 4];
            const float4 qb = *(const float4*)&Qs[tq * 2 + 1][h4 * 4];
#pragma unroll
            for (int j = 0; j < 4; j++) {
                const float4 kv = *(const float4*)&Ks[tk + 32 * j][h4 * 4];
                s[0][j] = fmaf(tanh_fast(qa.x + kv.x), w4.x, s[0][j]);
                s[0][j] = fmaf(tanh_fast(qa.y + kv.y), w4.y, s[0][j]);
                s[0][j] = fmaf(tanh_fast(qa.z + kv.z), w4.z, s[0][j]);
                s[0][j] = fmaf(tanh_fast(qa.w + kv.w), w4.w, s[0][j]);
                s[1][j] = fmaf(tanh_fast(qb.x + kv.x), w4.x, s[1][j]);
                s[1][j] = fmaf(tanh_fast(qb.y + kv.y), w4.y, s[1][j]);
                s[1][j] = fmaf(tanh_fast(qb.z + kv.z), w4.z, s[1][j]);
                s[1][j] = fmaf(tanh_fast(qb.w + kv.w), w4.w, s[1][j]);
            }
        }
        __syncthreads();
    }

    // ---------------- masked softmax (warp-local, 2 rows/warp) ----------------
    const int vlen = valid_lens[b];
#pragma unroll
    for (int r = 0; r < 2; r++)
#pragma unroll
        for (int j = 0; j < 4; j++)
            if (tk + 32 * j >= vlen) s[r][j] = -1e6f;

    float m0 = fmaxf(fmaxf(s[0][0], s[0][1]), fmaxf(s[0][2], s[0][3]));
    float m1 = fmaxf(fmaxf(s[1][0], s[1][1]), fmaxf(s[1][2], s[1][3]));
#pragma unroll
    for (int off = 16; off > 0; off >>= 1) {
        m0 = fmaxf(m0, __shfl_xor_sync(0xFFFFFFFFu, m0, off));
        m1 = fmaxf(m1, __shfl_xor_sync(0xFFFFFFFFu, m1, off));
    }
    float sum0 = 0.0f, sum1 = 0.0f;
#pragma unroll
    for (int j = 0; j < 4; j++) {
        s[0][j] = __expf(s[0][j] - m0); sum0 += s[0][j];
        s[1][j] = __expf(s[1][j] - m1); sum1 += s[1][j];
    }
#pragma unroll
    for (int off = 16; off > 0; off >>= 1) {
        sum0 += __shfl_xor_sync(0xFFFFFFFFu, sum0, off);
        sum1 += __shfl_xor_sync(0xFFFFFFFFu, sum1, off);
    }
    const float r0 = 1.0f / sum0, r1 = 1.0f / sum1;
#pragma unroll
    for (int j = 0; j < 4; j++) {
        attnT[tk + 32 * j][tq * 2]     = s[0][j] * r0;
        attnT[tk + 32 * j][tq * 2 + 1] = s[1][j] * r1;
    }
    __syncthreads();

    // ---------------- Phase B: out[16,512] = attn[16,128] @ V[128,512] --------
    const int d0 = tid * 2;                       // each thread: 2 d-columns
    const float* Vb = values + b * KDIM * DDIM;
    float2 acc[16];
#pragma unroll
    for (int q = 0; q < 16; q++) { acc[q].x = 0.0f; acc[q].y = 0.0f; }

#pragma unroll 2
    for (int k = 0; k < KDIM; ++k) {
        const float2 v = *(const float2*)&Vb[k * DDIM + d0];
        float a[16];
        *(float4*)&a[0]  = *(const float4*)&attnT[k][0];
        *(float4*)&a[4]  = *(const float4*)&attnT[k][4];
        *(float4*)&a[8]  = *(const float4*)&attnT[k][8];
        *(float4*)&a[12] = *(const float4*)&attnT[k][12];
#pragma unroll
        for (int q = 0; q < 16; q++) {
            acc[q].x = fmaf(a[q], v.x, acc[q].x);
            acc[q].y = fmaf(a[q], v.y, acc[q].y);
        }
    }

    float* Ob = out + (b * QDIM + qt * 16) * DDIM;
#pragma unroll
    for (int q = 0; q < 16; q++)
        *(float2*)&Ob[q * DDIM + d0] = acc[q];
}

// ----------------------------------------------------------------------------
extern "C" void kernel_launch(void* const* d_in, const int* in_sizes, int n_in,
                              void* d_out, int out_size)
{
    const float* queries    = (const float*)d_in[0];
    const float* keys       = (const float*)d_in[1];
    const float* values     = (const float*)d_in[2];
    const int*   valid_lens = (const int*)d_in[3];
    const float* Wq         = (const float*)d_in[4];
    const float* Wk         = (const float*)d_in[5];
    const float* wv         = (const float*)d_in[6];
    float* out = (float*)d_out;

    // both projections in one launch: grid (N/128=4, M/128=16, 2)
    sgemm_proj<<<dim3(4, 16, 2), 256>>>(queries, keys, Wq, Wk);
    // fused scores + softmax + AV: grid (8 q-tiles, 16 batches)
    attn_kernel<<<dim3(8, 16), 256>>>(values, valid_lens, wv, out);
}

// round 4
// speedup vs baseline: 1.1454x; 1.1454x over previous
#include <cuda_runtime.h>
#include <cstdint>

// ============================================================================
// AdditiveAttention: out = softmax_mask( sum_h tanh(Q@Wq + K@Wk) * wv ) @ V
// B=16, Q=128, K=128, D=512, H=512
//   kernel 1 (sgemm_proj): Qp = queries@Wq, Kp = keys@Wk  (one launch, z=0/1)
//   kernel 2 (attn_kernel): 512 threads, 16 warps; warp = 1 q-row for scores,
//                           thread = 1 d-column for AV. Register double-buffered
//                           h-chunks of 64. attnT aliases Ks (smem pool) to fit
//                           the 48KB static smem limit.
// ============================================================================

#define BDIM 16
#define QDIM 128
#define KDIM 128
#define DDIM 512
#define HDIM 512

__device__ float g_Qp[BDIM * QDIM * HDIM];   // [b*128+q][h], 4 MB
__device__ float g_Kp[BDIM * KDIM * HDIM];   // [b*128+k][h], 4 MB

__device__ __forceinline__ float tanh_fast(float x) {
    float y;
    asm("tanh.approx.f32 %0, %1;" : "=f"(y) : "f"(x));
    return y;
}

// ----------------------------------------------------------------------------
// Kernel 1: C[M,N] = A[M,K] * W[K,N]   with M=2048, K=512, N=512
// 128x128 tile, BK=16, 256 threads, 8x8 micro-tile, register prefetch.
// ----------------------------------------------------------------------------
__global__ __launch_bounds__(256, 1) void sgemm_proj(
    const float* __restrict__ Aq, const float* __restrict__ Ak,
    const float* __restrict__ Wq, const float* __restrict__ Wk)
{
    const int K = DDIM;          // 512
    const int N = HDIM;          // 512

    const float* A = blockIdx.z ? Ak : Aq;
    const float* W = blockIdx.z ? Wk : Wq;
    float* C = blockIdx.z ? g_Kp : g_Qp;

    __shared__ __align__(16) float As[16][132];   // transposed: As[k][m]
    __shared__ __align__(16) float Ws[16][128];   // Ws[k][n]

    const int tid = threadIdx.x;
    const int tx = tid & 15;
    const int ty = tid >> 4;
    const int m0 = blockIdx.y * 128;
    const int n0 = blockIdx.x * 128;

    const int arow = tid >> 2;
    const int ac   = (tid & 3) << 2;
    const int wk   = tid >> 5;
    const int wn   = (tid & 31) << 2;

    float acc[8][8];
#pragma unroll
    for (int i = 0; i < 8; i++)
#pragma unroll
        for (int j = 0; j < 8; j++) acc[i][j] = 0.0f;

    float4 pa0, pa1, pw0, pw1;

    pa0 = *(const float4*)&A[(m0 + arow) * K + 0 + ac];
    pa1 = *(const float4*)&A[(m0 + arow + 64) * K + 0 + ac];
    pw0 = *(const float4*)&W[(0 + wk) * N + n0 + wn];
    pw1 = *(const float4*)&W[(0 + wk + 8) * N + n0 + wn];

    As[ac + 0][arow] = pa0.x; As[ac + 1][arow] = pa0.y;
    As[ac + 2][arow] = pa0.z; As[ac + 3][arow] = pa0.w;
    As[ac + 0][arow + 64] = pa1.x; As[ac + 1][arow + 64] = pa1.y;
    As[ac + 2][arow + 64] = pa1.z; As[ac + 3][arow + 64] = pa1.w;
    *(float4*)&Ws[wk][wn] = pw0;
    *(float4*)&Ws[wk + 8][wn] = pw1;
    __syncthreads();

    const int NIT = K / 16;   // 32
    for (int it = 0; it < NIT; ++it) {
        if (it + 1 < NIT) {
            const int kt = (it + 1) * 16;
            pa0 = *(const float4*)&A[(m0 + arow) * K + kt + ac];
            pa1 = *(const float4*)&A[(m0 + arow + 64) * K + kt + ac];
            pw0 = *(const float4*)&W[(kt + wk) * N + n0 + wn];
            pw1 = *(const float4*)&W[(kt + wk + 8) * N + n0 + wn];
        }
#pragma unroll
        for (int kk = 0; kk < 16; ++kk) {
            float a[8], b[8];
            *(float4*)&a[0] = *(const float4*)&As[kk][ty * 8];
            *(float4*)&a[4] = *(const float4*)&As[kk][ty * 8 + 4];
            *(float4*)&b[0] = *(const float4*)&Ws[kk][tx * 8];
            *(float4*)&b[4] = *(const float4*)&Ws[kk][tx * 8 + 4];
#pragma unroll
            for (int i = 0; i < 8; i++)
#pragma unroll
                for (int j = 0; j < 8; j++)
                    acc[i][j] = fmaf(a[i], b[j], acc[i][j]);
        }
        __syncthreads();
        if (it + 1 < NIT) {
            As[ac + 0][arow] = pa0.x; As[ac + 1][arow] = pa0.y;
            As[ac + 2][arow] = pa0.z; As[ac + 3][arow] = pa0.w;
            As[ac + 0][arow + 64] = pa1.x; As[ac + 1][arow + 64] = pa1.y;
            As[ac + 2][arow + 64] = pa1.z; As[ac + 3][arow + 64] = pa1.w;
            *(float4*)&Ws[wk][wn] = pw0;
            *(float4*)&Ws[wk + 8][wn] = pw1;
            __syncthreads();
        }
    }

#pragma unroll
    for (int i = 0; i < 8; i++) {
        float* crow = &C[(m0 + ty * 8 + i) * N + n0 + tx * 8];
        *(float4*)&crow[0] = *(float4*)&acc[i][0];
        *(float4*)&crow[4] = *(float4*)&acc[i][4];
    }
}

// ----------------------------------------------------------------------------
// Kernel 2: fused scores + masked softmax + attn@V
// grid = (8 q-tiles, 16 batches), 512 threads (16 warps).
// Phase A: warp w owns q-row w; lane tk owns k in {tk, tk+32, tk+64, tk+96}.
//          h staged in chunks of HC=64 with register double-buffering.
// Phase B: thread tid owns d-column tid (512 threads = 512 d).
// Shared-memory pool (41.2 KB): [Ks | Qs | wvs], with attnT aliasing the Ks
// region (Ks is dead after Phase A's final __syncthreads()).
// ----------------------------------------------------------------------------
#define HC 64
#define KS_STRIDE 68   // 68 % 32 == 4 -> conflict-free LDS.128 pattern
#define POOL_FLOATS (128 * KS_STRIDE + 16 * KS_STRIDE + HDIM)   // 10304 = 41.2KB

__global__ __launch_bounds__(512, 1) void attn_kernel(
    const float* __restrict__ values,
    const int* __restrict__ valid_lens,
    const float* __restrict__ wv,
    float* __restrict__ out)
{
    const int b   = blockIdx.y;
    const int qt  = blockIdx.x;       // 0..7, 16 q-rows each
    const int tid = threadIdx.x;
    const int tk  = tid & 31;         // lane
    const int w   = tid >> 5;         // warp id 0..15 -> q row w

    __shared__ __align__(16) float pool[POOL_FLOATS];
    float (*Ks)[KS_STRIDE] = (float(*)[KS_STRIDE])&pool[0];                 // 128x68
    float (*Qs)[KS_STRIDE] = (float(*)[KS_STRIDE])&pool[128 * KS_STRIDE];   // 16x68
    float* wvs = &pool[144 * KS_STRIDE];                                    // 512
    float (*attnT)[20] = (float(*)[20])&pool[0];   // aliases Ks (dead after A)

    // load wv once (512 floats = 128 float4)
    if (tid < 128)
        *(float4*)&wvs[tid * 4] = *(const float4*)&wv[tid * 4];

    const float* Qp = g_Qp + (b * QDIM + qt * 16) * HDIM;
    const float* Kp = g_Kp + b * KDIM * HDIM;

    // chunk-load coordinates (float4 granularity)
    const int kq_row = tid >> 4;            // 0..31  (Ks rows, 4 groups of 32)
    const int kq_c4  = (tid & 15);          // 0..15  -> float4 index in 64-float chunk
    const int q_row  = tid >> 4;            // 0..15  for tid<256 (16 float4 per row)
    const int q_c4   = tid & 15;            // 0..15

    float4 pk[4];
    float4 pq;

    // ---- prefetch chunk 0 ----
#pragma unroll
    for (int i = 0; i < 4; i++)
        pk[i] = *(const float4*)&Kp[(kq_row + 32 * i) * HDIM + 0 + kq_c4 * 4];
    if (tid < 256)
        pq = *(const float4*)&Qp[q_row * HDIM + 0 + q_c4 * 4];

#pragma unroll
    for (int i = 0; i < 4; i++)
        *(float4*)&Ks[kq_row + 32 * i][kq_c4 * 4] = pk[i];
    if (tid < 256)
        *(float4*)&Qs[q_row][q_c4 * 4] = pq;
    __syncthreads();

    float s[4];
#pragma unroll
    for (int j = 0; j < 4; j++) s[j] = 0.0f;

    // ---------------- Phase A: scores over h chunks ----------------
    const int NCH = HDIM / HC;   // 8
    for (int hc = 0; hc < NCH; ++hc) {
        const int h0 = hc * HC;
        if (hc + 1 < NCH) {
            const int hn = h0 + HC;
#pragma unroll
            for (int i = 0; i < 4; i++)
                pk[i] = *(const float4*)&Kp[(kq_row + 32 * i) * HDIM + hn + kq_c4 * 4];
            if (tid < 256)
                pq = *(const float4*)&Qp[q_row * HDIM + hn + q_c4 * 4];
        }

#pragma unroll
        for (int h4 = 0; h4 < HC / 4; ++h4) {
            const float4 w4 = *(const float4*)&wvs[h0 + h4 * 4];
            const float4 qa = *(const float4*)&Qs[w][h4 * 4];
#pragma unroll
            for (int j = 0; j < 4; j++) {
                const float4 kv = *(const float4*)&Ks[tk + 32 * j][h4 * 4];
                s[j] = fmaf(tanh_fast(qa.x + kv.x), w4.x, s[j]);
                s[j] = fmaf(tanh_fast(qa.y + kv.y), w4.y, s[j]);
                s[j] = fmaf(tanh_fast(qa.z + kv.z), w4.z, s[j]);
                s[j] = fmaf(tanh_fast(qa.w + kv.w), w4.w, s[j]);
            }
        }
        __syncthreads();   // Ks/Qs dead here on last iter -> attnT alias safe
        if (hc + 1 < NCH) {
#pragma unroll
            for (int i = 0; i < 4; i++)
                *(float4*)&Ks[kq_row + 32 * i][kq_c4 * 4] = pk[i];
            if (tid < 256)
                *(float4*)&Qs[q_row][q_c4 * 4] = pq;
            __syncthreads();
        }
    }

    // ---------------- masked softmax (warp-local, 1 row/warp) ----------------
    const int vlen = valid_lens[b];
#pragma unroll
    for (int j = 0; j < 4; j++)
        if (tk + 32 * j >= vlen) s[j] = -1e6f;

    float m = fmaxf(fmaxf(s[0], s[1]), fmaxf(s[2], s[3]));
#pragma unroll
    for (int off = 16; off > 0; off >>= 1)
        m = fmaxf(m, __shfl_xor_sync(0xFFFFFFFFu, m, off));
    float sum = 0.0f;
#pragma unroll
    for (int j = 0; j < 4; j++) {
        s[j] = __expf(s[j] - m);
        sum += s[j];
    }
#pragma unroll
    for (int off = 16; off > 0; off >>= 1)
        sum += __shfl_xor_sync(0xFFFFFFFFu, sum, off);
    const float rs = 1.0f / sum;
#pragma unroll
    for (int j = 0; j < 4; j++)
        attnT[tk + 32 * j][w] = s[j] * rs;
    __syncthreads();

    // ---------------- Phase B: out[16,512] = attn[16,128] @ V[128,512] --------
    const int d = tid;                          // one d-column per thread
    const float* Vb = values + b * KDIM * DDIM + d;
    float acc[16];
#pragma unroll
    for (int q = 0; q < 16; q++) acc[q] = 0.0f;

#pragma unroll 4
    for (int k = 0; k < KDIM; ++k) {
        const float v = Vb[k * DDIM];
        float a[16];
        *(float4*)&a[0]  = *(const float4*)&attnT[k][0];
        *(float4*)&a[4]  = *(const float4*)&attnT[k][4];
        *(float4*)&a[8]  = *(const float4*)&attnT[k][8];
        *(float4*)&a[12] = *(const float4*)&attnT[k][12];
#pragma unroll
        for (int q = 0; q < 16; q++)
            acc[q] = fmaf(a[q], v, acc[q]);
    }

    float* Ob = out + (b * QDIM + qt * 16) * DDIM + d;
#pragma unroll
    for (int q = 0; q < 16; q++)
        Ob[q * DDIM] = acc[q];
}

// ----------------------------------------------------------------------------
extern "C" void kernel_launch(void* const* d_in, const int* in_sizes, int n_in,
                              void* d_out, int out_size)
{
    const float* queries    = (const float*)d_in[0];
    const float* keys       = (const float*)d_in[1];
    const float* values     = (const float*)d_in[2];
    const int*   valid_lens = (const int*)d_in[3];
    const float* Wq         = (const float*)d_in[4];
    const float* Wk         = (const float*)d_in[5];
    const float* wv         = (const float*)d_in[6];
    float* out = (float*)d_out;

    sgemm_proj<<<dim3(4, 16, 2), 256>>>(queries, keys, Wq, Wk);
    attn_kernel<<<dim3(8, 16), 512>>>(values, valid_lens, wv, out);
}